// round 16
// baseline (speedup 1.0000x reference)
#include <cuda_runtime.h>
#include <cuda_bf16.h>
#include <math.h>
#include <stdint.h>

#define BB 16
#define NN 196
#define DD 512
#define MM 20
#define HH 8
#define HD 64
#define RTOT (BB*NN)   /* 3136 */
#define WROWS 2560     /* in_w 1536 + out_w 512 + w1 512 */

// ---------------- scratch (device globals; no allocation) ----------------
__device__ float g_qkv[RTOT*3*DD];
__device__ float g_h[RTOT*DD];
__device__ __nv_bfloat16 g_A1[RTOT*DD], g_A2[RTOT*DD], g_A3[RTOT*DD];
__device__ __nv_bfloat16 g_B1[RTOT*DD], g_B2[RTOT*DD], g_B3[RTOT*DD];
__device__ __nv_bfloat16 g_W1[WROWS*DD], g_W2[WROWS*DD], g_W3[WROWS*DD];

// ---------------- warp helpers ----------------
__device__ __forceinline__ float warp_sum(float v){
#pragma unroll
    for (int off=16; off; off>>=1) v += __shfl_xor_sync(0xffffffffu, v, off);
    return v;
}
__device__ __forceinline__ float warp_max(float v){
#pragma unroll
    for (int off=16; off; off>>=1) v = fmaxf(v, __shfl_xor_sync(0xffffffffu, v, off));
    return v;
}

// ---------------- mma.sync / cp.async helpers ----------------
__device__ __forceinline__ uint32_t smem_u32(const void* p){
    uint32_t a;
    asm("{ .reg .u64 t; cvta.to.shared.u64 t, %1; cvt.u32.u64 %0, t; }" : "=r"(a) : "l"(p));
    return a;
}
__device__ __forceinline__ void ldm4(uint32_t* r, uint32_t addr){
    asm volatile("ldmatrix.sync.aligned.m8n8.x4.shared.b16 {%0,%1,%2,%3}, [%4];"
        : "=r"(r[0]),"=r"(r[1]),"=r"(r[2]),"=r"(r[3]) : "r"(addr));
}
__device__ __forceinline__ void mma16816(float* c, const uint32_t* a, const uint32_t* b){
    asm volatile("mma.sync.aligned.m16n8k16.row.col.f32.bf16.bf16.f32 "
        "{%0,%1,%2,%3}, {%4,%5,%6,%7}, {%8,%9}, {%0,%1,%2,%3};"
        : "+f"(c[0]),"+f"(c[1]),"+f"(c[2]),"+f"(c[3])
        : "r"(a[0]),"r"(a[1]),"r"(a[2]),"r"(a[3]), "r"(b[0]),"r"(b[1]));
}
__device__ __forceinline__ void cp16(uint32_t dst, const void* src){
    uint64_t g = __cvta_generic_to_global(src);
    asm volatile("cp.async.ca.shared.global [%0], [%1], 16;" :: "r"(dst), "l"(g) : "memory");
}

// 3-way bf16 cascade split: v = h1 + h2 + h3 + O(2^-27 |v|)
__device__ __forceinline__ void split3(float v, uint32_t& t1, uint32_t& t2, uint32_t& t3){
    __nv_bfloat16 h1 = __float2bfloat16_rn(v);
    float r1 = v - __bfloat162float(h1);
    __nv_bfloat16 h2 = __float2bfloat16_rn(r1);
    float r2 = r1 - __bfloat162float(h2);
    __nv_bfloat16 h3 = __float2bfloat16_rn(r2);
    t1 = (uint32_t)__bfloat16_as_ushort(h1);
    t2 = (uint32_t)__bfloat16_as_ushort(h2);
    t3 = (uint32_t)__bfloat16_as_ushort(h3);
}
__device__ __forceinline__ __nv_bfloat16 asbf(uint32_t t){
    return __ushort_as_bfloat16((unsigned short)t);
}

// ---------------- combined pre-split: weights + F in ONE launch -------------
#define SPLIT_W4 (WROWS*128)
#define SPLIT_T4 (SPLIT_W4 + RTOT*128)

__global__ void __launch_bounds__(256) split_all(
    const float* __restrict__ in_w, const float* __restrict__ out_w,
    const float* __restrict__ w1, const float* __restrict__ F)
{
    int i = blockIdx.x*256 + threadIdx.x;
    if (i >= SPLIT_T4) return;
    const float* src; size_t off;
    __nv_bfloat16 *d1, *d2, *d3; size_t dof;
    if (i < SPLIT_W4){
        int row = i >> 7;
        if (row < 1536){ src = in_w;  off = i; }
        else if (row < 2048){ src = out_w; off = i - (size_t)1536*128; }
        else { src = w1; off = i - (size_t)2048*128; }
        d1 = g_W1; d2 = g_W2; d3 = g_W3; dof = i;
    } else {
        src = F; off = i - SPLIT_W4;
        d1 = g_A1; d2 = g_A2; d3 = g_A3; dof = i - SPLIT_W4;
    }
    float4 v = ((const float4*)src)[off];
    uint32_t x1,x2,x3, y1,y2,y3, z1,z2,z3, u1,u2,u3;
    split3(v.x, x1,x2,x3); split3(v.y, y1,y2,y3);
    split3(v.z, z1,z2,z3); split3(v.w, u1,u2,u3);
    *(uint2*)&d1[dof*4] = make_uint2(x1|(y1<<16), z1|(u1<<16));
    *(uint2*)&d2[dof*4] = make_uint2(x2|(y2<<16), z2|(u2<<16));
    *(uint2*)&d3[dof*4] = make_uint2(x3|(y3<<16), z3|(u3<<16));
}

// ---------------- pure-bf16 tensor-core GEMM, 128x128 tile, 2-stage ---------
// 8 warps (4m x 2n), warp tile 32x64. Stage = 6 x (128 rows x 32 bf16) = 48KB.
#define TILE_B   8192                    /* 128 rows x 32 bf16 x 2B */
#define STAGE_B  (6*TILE_B)              /* 49152 */
#define GSM_SIZE (2*STAGE_B)             /* 98304; 2 CTAs = 196608 <= 228KB */

template<bool RES, bool SPLITOUT>
__global__ void __launch_bounds__(256) gemm_bf(
    const __nv_bfloat16* __restrict__ A1, const __nv_bfloat16* __restrict__ A2,
    const __nv_bfloat16* __restrict__ A3,
    const __nv_bfloat16* __restrict__ W1, const __nv_bfloat16* __restrict__ W2,
    const __nv_bfloat16* __restrict__ W3,
    const float* __restrict__ bias, const float* __restrict__ res,
    float* __restrict__ C, int R, int K, int O)
{
    extern __shared__ __align__(128) char smem[];
    const uint32_t sb = smem_u32(smem);
    const int tid = threadIdx.x, lane = tid & 31, wid = tid >> 5;
    const int rb = blockIdx.y * 128, ob = blockIdx.x * 128;
    const int wm = wid & 3, wn = wid >> 2;   // warp tile rows wm*32, cols wn*64

    float acc[2][8][4];
#pragma unroll
    for (int i=0;i<2;i++)
#pragma unroll
        for (int j=0;j<8;j++)
#pragma unroll
            for (int q=0;q<4;q++) acc[i][j][q]=0.f;

    const __nv_bfloat16* As[3] = {A1, A2, A3};
    const __nv_bfloat16* Ws[3] = {W1, W2, W3};

    // per-thread copy coordinates: f = tid + j*256, row = f>>2 (0..127), q = f&3
    const int cr = tid >> 2, cq = tid & 3;
    int gra0 = rb + cr;      if (gra0 >= R) gra0 = R - 1;
    int gra1 = rb + cr + 64; if (gra1 >= R) gra1 = R - 1;
    uint32_t coff0 = (uint32_t)(cr*64 + cq*16);        coff0 ^= (coff0>>3) & 0x30u;
    uint32_t coff1 = (uint32_t)((cr+64)*64 + cq*16);   coff1 ^= (coff1>>3) & 0x30u;

    auto issue_chunk = [&](int c){
        const uint32_t base = sb + (uint32_t)(c & 1)*STAGE_B;
        const int k0 = c*32;
#pragma unroll
        for (int t = 0; t < 3; t++){
            cp16(base + t*TILE_B + coff0, As[t] + (size_t)gra0*K + k0 + cq*8);
            cp16(base + t*TILE_B + coff1, As[t] + (size_t)gra1*K + k0 + cq*8);
        }
#pragma unroll
        for (int t = 0; t < 3; t++){
            cp16(base + (3+t)*TILE_B + coff0, Ws[t] + (size_t)(ob + cr)*K + k0 + cq*8);
            cp16(base + (3+t)*TILE_B + coff1, Ws[t] + (size_t)(ob + cr + 64)*K + k0 + cq*8);
        }
        asm volatile("cp.async.commit_group;" ::: "memory");
    };

    const int NTc = K / 32;
    issue_chunk(0);

    const int npair[3] = {3, 2, 1};   // a1*{w1,w2,w3}, a2*{w1,w2}, a3*{w1}

    for (int c = 0; c < NTc; c++){
        if (c+1 < NTc){
            issue_chunk(c+1);
            asm volatile("cp.async.wait_group 1;" ::: "memory");
        } else {
            asm volatile("cp.async.wait_group 0;" ::: "memory");
        }
        __syncthreads();

        const uint32_t stg = sb + (uint32_t)(c & 1)*STAGE_B;
#pragma unroll
        for (int ks = 0; ks < 2; ks++){
#pragma unroll
            for (int ai = 0; ai < 3; ai++){
                uint32_t afr[2][4];
#pragma unroll
                for (int mt = 0; mt < 2; mt++){
                    uint32_t row = (uint32_t)(wm*32 + mt*16 + (lane & 15));
                    uint32_t off = row*64 + (uint32_t)(ks*32) + (uint32_t)((lane >> 4) << 4);
                    off ^= (off >> 3) & 0x30u;
                    ldm4(afr[mt], stg + ai*TILE_B + off);
                }
#pragma unroll
                for (int wj = 0; wj < 3; wj++){
                    if (wj >= npair[ai]) break;
                    uint32_t bfr[8][2];
#pragma unroll
                    for (int nt2 = 0; nt2 < 4; nt2++){
                        uint32_t row = (uint32_t)(wn*64 + nt2*16 + ((lane >> 4) << 3) + (lane & 7));
                        uint32_t off = row*64 + (uint32_t)(ks*32) + (uint32_t)(((lane >> 3) & 1) << 4);
                        off ^= (off >> 3) & 0x30u;
                        uint32_t r4[4];
                        ldm4(r4, stg + (3+wj)*TILE_B + off);
                        bfr[nt2*2][0]=r4[0];   bfr[nt2*2][1]=r4[1];
                        bfr[nt2*2+1][0]=r4[2]; bfr[nt2*2+1][1]=r4[3];
                    }
#pragma unroll
                    for (int mt = 0; mt < 2; mt++)
#pragma unroll
                        for (int nt = 0; nt < 8; nt++)
                            mma16816(acc[mt][nt], afr[mt], bfr[nt]);
                }
            }
        }
        __syncthreads();
    }

    // ---- epilogue: stage via SMEM (stride 129) then coalesced global write --
    float* Cs = (float*)smem;
    {
        const int r0 = wm*32 + (lane >> 2);
        const int c0 = wn*64 + 2*(lane & 3);
#pragma unroll
        for (int mt = 0; mt < 2; mt++)
#pragma unroll
            for (int nt = 0; nt < 8; nt++){
                int row = r0 + mt*16, col = c0 + nt*8;
                Cs[row*129 + col]       = acc[mt][nt][0];
                Cs[row*129 + col + 1]   = acc[mt][nt][1];
                Cs[(row+8)*129 + col]   = acc[mt][nt][2];
                Cs[(row+8)*129 + col+1] = acc[mt][nt][3];
            }
    }
    __syncthreads();

    for (int idx = tid; idx < 128*128; idx += 256){
        int row = idx >> 7, c = idx & 127;
        int r = rb + row;
        if (r < R){
            float v = Cs[row*129 + c] + bias[ob + c];
            size_t g = (size_t)r*O + ob + c;
            if (RES) v += res[g];
            if (SPLITOUT){
                uint32_t t1,t2,t3;
                split3(v, t1,t2,t3);
                g_B1[g] = asbf(t1); g_B2[g] = asbf(t2); g_B3[g] = asbf(t3);
            } else {
                C[g] = v;
            }
        }
    }
}

// ---------------- attention: cp.async double-buffered K/V ------------------
#define ASM_Q   0
#define ASM_K0  1904
#define ASM_K1  5236
#define ASM_V0  8568
#define ASM_V1  11900
#define ASM_S   15232
#define ASM_FLOATS 16688   /* x4 = 66752 bytes */

__global__ void __launch_bounds__(256) attn_kernel()
{
    extern __shared__ __align__(16) float asmem[];
    const int qc = blockIdx.x, h = blockIdx.y, b = blockIdx.z;
    const int r0 = qc*28;
    const int tid = threadIdx.x, lane = tid & 31, w = tid >> 5;

    float* Qs = asmem + ASM_Q;
    float* S  = asmem + ASM_S;
    const uint32_t kbu[2] = {smem_u32(asmem + ASM_K0), smem_u32(asmem + ASM_K1)};
    const uint32_t vbu[2] = {smem_u32(asmem + ASM_V0), smem_u32(asmem + ASM_V1)};

    auto issue = [&](int t){
        const int buf = t & 1;
        for (int idx = tid; idx < 784; idx += 256){
            int j = idx >> 4, seg = idx & 15;
            size_t gb = (size_t)(b*NN + t*49 + j)*1536 + h*64 + seg*4;
            cp16(kbu[buf] + j*272 + seg*16, g_qkv + gb + 512);
            cp16(vbu[buf] + j*272 + seg*16, g_qkv + gb + 1024);
        }
        asm volatile("cp.async.commit_group;" ::: "memory");
    };

    issue(0);
    for (int idx=tid; idx<28*64; idx+=256){
        int row = idx>>6, kx = idx&63;
        Qs[row*68+kx] = g_qkv[(size_t)(b*NN + r0+row)*1536 + h*64 + kx];
    }

    const int nrows = (w<4)?4:3;
    float mrun[4], lrun[4], o0[4], o1[4];
#pragma unroll
    for (int rr=0; rr<4; rr++){ mrun[rr]=-1e30f; lrun[rr]=0.f; o0[rr]=0.f; o1[rr]=0.f; }

    const int srow = tid >> 3, jg = tid & 7;

    for (int t=0;t<4;t++){
        __syncthreads();
        if (t<3){
            issue(t+1);
            asm volatile("cp.async.wait_group 1;" ::: "memory");
        } else {
            asm volatile("cp.async.wait_group 0;" ::: "memory");
        }
        __syncthreads();

        const int buf = t & 1;
        const float* Ks = asmem + (buf ? ASM_K1 : ASM_K0);
        const float* Vs = asmem + (buf ? ASM_V1 : ASM_V0);

        if (srow < 28){
            float acc[7];
#pragma unroll
            for (int jj=0;jj<7;jj++) acc[jj]=0.f;
            const float4* q4 = (const float4*)&Qs[srow*68];
#pragma unroll
            for (int kx=0; kx<16; kx++){
                float4 qa = q4[kx];
#pragma unroll
                for (int jj=0;jj<7;jj++){
                    int j = jg + 8*jj;
                    if (j < 49){
                        float4 ka = *(const float4*)&Ks[j*68 + kx*4];
                        acc[jj] += qa.x*ka.x + qa.y*ka.y + qa.z*ka.z + qa.w*ka.w;
                    }
                }
            }
#pragma unroll
            for (int jj=0;jj<7;jj++){
                int j = jg + 8*jj;
                if (j < 49) S[srow*52+j] = acc[jj]*0.125f;
            }
        }
        __syncthreads();

#pragma unroll
        for (int rr=0; rr<4; rr++){
            if (rr >= nrows) break;
            int row = w + 8*rr;
            float s0 = (lane<49) ? S[row*52+lane]    : -1e30f;
            float s1 = (lane<17) ? S[row*52+lane+32] : -1e30f;
            float tm = warp_max(fmaxf(s0,s1));
            float mnew = fmaxf(mrun[rr], tm);
            float alpha = __expf(mrun[rr]-mnew);
            float p0 = (lane<49) ? __expf(s0-mnew) : 0.f;
            float p1 = (lane<17) ? __expf(s1-mnew) : 0.f;
            float psum = warp_sum(p0+p1);
            lrun[rr] = lrun[rr]*alpha + psum;
            mrun[rr] = mnew;
            if (lane<49) S[row*52+lane]    = p0;
            if (lane<17) S[row*52+lane+32] = p1;
            o0[rr]*=alpha; o1[rr]*=alpha;
        }
        __syncwarp();

#pragma unroll 3
        for (int j4=0; j4<12; j4++){
            const int jb2 = j4*4;
            float2 va0 = *(const float2*)&Vs[(jb2+0)*68 + 2*lane];
            float2 va1 = *(const float2*)&Vs[(jb2+1)*68 + 2*lane];
            float2 va2 = *(const float2*)&Vs[(jb2+2)*68 + 2*lane];
            float2 va3 = *(const float2*)&Vs[(jb2+3)*68 + 2*lane];
#pragma unroll
            for (int rr=0; rr<4; rr++){
                if (rr >= nrows) break;
                float4 p = *(const float4*)&S[(w + 8*rr)*52 + jb2];
                o0[rr] += p.x*va0.x + p.y*va1.x + p.z*va2.x + p.w*va3.x;
                o1[rr] += p.x*va0.y + p.y*va1.y + p.z*va2.y + p.w*va3.y;
            }
        }
        {
            float2 v48 = *(const float2*)&Vs[48*68 + 2*lane];
#pragma unroll
            for (int rr=0; rr<4; rr++){
                if (rr >= nrows) break;
                float pj = S[(w + 8*rr)*52 + 48];
                o0[rr] += pj * v48.x;
                o1[rr] += pj * v48.y;
            }
        }
    }
    for (int rr=0; rr<nrows; rr++){
        int row = w + 8*rr;
        float inv = 1.f/lrun[rr];
        size_t base = (size_t)(b*NN + r0+row)*512 + h*64 + 2*lane;
        uint32_t t1,t2,t3;
        split3(o0[rr]*inv, t1,t2,t3);
        g_A1[base] = asbf(t1); g_A2[base] = asbf(t2); g_A3[base] = asbf(t3);
        split3(o1[rr]*inv, t1,t2,t3);
        g_A1[base+1] = asbf(t1); g_A2[base+1] = asbf(t2); g_A3[base+1] = asbf(t3);
    }
}

// ---------------- fused LN + GELU + w2 + decompose (R13 version) ------------
__global__ void __launch_bounds__(256) ln_decomp(
    const float* __restrict__ hin, const float* __restrict__ lng,
    const float* __restrict__ lnb, const float* __restrict__ w2,
    const float* __restrict__ b2,
    const float* __restrict__ F, const float* __restrict__ tpl,
    const int* __restrict__ kptr, float* __restrict__ out)
{
    const int r = blockIdx.x, tid = threadIdx.x, lane = tid&31, w = tid>>5;
    __shared__ float fs[512];
    __shared__ float gs[512];
    __shared__ float red[16];
    __shared__ int hist[8][256];
    __shared__ unsigned int thr_s[MM];
    __shared__ float scale_s[MM];
    __shared__ unsigned int eqmask_s[MM][16];

    float x0 = hin[(size_t)r*512 + tid];
    float x1 = hin[(size_t)r*512 + tid + 256];
    fs[tid]     = F[(size_t)r*512 + tid];
    fs[tid+256] = F[(size_t)r*512 + tid + 256];

    float s  = warp_sum(x0 + x1);
    float sq = warp_sum(x0*x0 + x1*x1);
    if (lane==0){ red[w]=s; red[w+8]=sq; }
    __syncthreads();
    if (tid==0){
        float S=0,Q=0;
#pragma unroll
        for (int i=0;i<8;i++){ S+=red[i]; Q+=red[i+8]; }
        red[0]=S; red[1]=Q;
    }
    __syncthreads();
    float mean = red[0]*(1.f/512.f);
    float var  = red[1]*(1.f/512.f) - mean*mean;
    float rstd = rsqrtf(var + 1e-5f);
    {
        float y0 = (x0-mean)*rstd*lng[tid]     + lnb[tid];
        float y1 = (x1-mean)*rstd*lng[tid+256] + lnb[tid+256];
        gs[tid]     = 0.5f*y0*(1.f+erff(y0*0.70710678118654752f));
        gs[tid+256] = 0.5f*y1*(1.f+erff(y1*0.70710678118654752f));
    }
    __syncthreads();

    const int kval = *kptr;   // 51
    const int nm = (w<4) ? 3 : 2;
    float qpv[3];
    for (int i=0; i<nm; i++){
        int m = w + 8*i;
        float acc = 0.f;
#pragma unroll
        for (int j=0;j<16;j++){
            int d = lane + 32*j;
            acc += gs[d]*w2[m*512+d];
        }
        qpv[i] = warp_sum(acc) + b2[m];
    }

    for (int i=0; i<nm; i++){
        int m = w + 8*i;
        float p[16]; unsigned int u[16];
#pragma unroll
        for (int j=0;j<16;j++){
            int d = lane + 32*j;
            p[j] = fs[d]*tpl[m*512+d];
            u[j] = __float_as_uint(fabsf(p[j]));
        }
        unsigned int pref=0u, pmask=0u; int kk = kval;
        const int shifts[4]  = {23,15,7,0};
        const unsigned int dmasks[4] = {0xFFu,0xFFu,0xFFu,0x7Fu};
#pragma unroll
        for (int ps=0; ps<4; ps++){
            const int sh = shifts[ps]; const unsigned int dm = dmasks[ps];
            for (int bI=lane; bI<256; bI+=32) hist[w][bI]=0;
            __syncwarp();
#pragma unroll
            for (int j=0;j<16;j++){
                if ((u[j] & pmask) == pref)
                    atomicAdd(&hist[w][(u[j]>>sh)&dm], 1);
            }
            __syncwarp();
            int base = 255 - 8*lane;
            int s8 = 0;
#pragma unroll
            for (int j=0;j<8;j++) s8 += hist[w][base-j];
            int incl = s8;
#pragma unroll
            for (int off=1; off<32; off<<=1){
                int v = __shfl_up_sync(0xffffffffu, incl, off);
                if (lane>=off) incl += v;
            }
            int excl = incl - s8;
            int dig = -1, kk2 = 0;
            if (excl < kk && incl >= kk){
                int run = excl;
#pragma unroll
                for (int j=0;j<8;j++){
                    int hc = hist[w][base-j];
                    if (dig<0 && run+hc >= kk){ dig = base-j; kk2 = kk-run; }
                    run += hc;
                }
            }
            unsigned int bal = __ballot_sync(0xffffffffu, dig>=0);
            int src = __ffs(bal)-1;
            dig = __shfl_sync(0xffffffffu, dig, src);
            kk  = __shfl_sync(0xffffffffu, kk2, src);
            pref  |= ((unsigned int)dig) << sh;
            pmask |= dm << sh;
            __syncwarp();
        }
        const unsigned int thr = pref;
        const int needeq = kk;

        if (lane<16) eqmask_s[m][lane]=0u;
        __syncwarp();
        float ss = 0.f; int eqbase = 0;
#pragma unroll
        for (int j=0;j<16;j++){
            bool eq = (u[j]==thr);
            unsigned int eb = __ballot_sync(0xffffffffu, eq);
            bool esel = eq && (eqbase + __popc(eb & ((1u<<lane)-1u)) < needeq);
            eqbase += __popc(eb);
            unsigned int sb2 = __ballot_sync(0xffffffffu, esel);
            if (lane==0) eqmask_s[m][j] = sb2;
            if (u[j] > thr || esel) ss += p[j]*p[j];
        }
        ss = warp_sum(ss);
        if (lane==0){
            float q = qpv[i];
            float nrm = fabsf(q)*sqrtf(ss);
            scale_s[m] = q / fmaxf(nrm, 1e-6f);
            thr_s[m]   = thr;
        }
    }
    __syncthreads();

    const size_t obase = (size_t)r * (512*MM);
    for (int base = tid*4; base < 512*MM; base += 1024){
        float4 vv;
        float* pv4 = (float*)&vv;
#pragma unroll
        for (int e=0;e<4;e++){
            int lin = base + e;
            int d = lin / MM, m = lin - d*MM;
            float pv = fs[d]*tpl[m*512+d];
            unsigned int uu = __float_as_uint(fabsf(pv));
            unsigned int thr = thr_s[m];
            bool sel = (uu > thr) ||
                       (uu == thr && ((eqmask_s[m][d>>5] >> (d&31)) & 1u));
            pv4[e] = sel ? pv*scale_s[m] : 0.f;
        }
        *(float4*)&out[obase + base] = vv;
    }
}

// ---------------- launch ----------------
extern "C" void kernel_launch(void* const* d_in, const int* in_sizes, int n_in,
                              void* d_out, int out_size)
{
    (void)in_sizes; (void)n_in; (void)out_size;
    const float* F     = (const float*)d_in[0];
    const float* in_w  = (const float*)d_in[1];
    const float* in_b  = (const float*)d_in[2];
    const float* out_w = (const float*)d_in[3];
    const float* out_b = (const float*)d_in[4];
    const float* w1    = (const float*)d_in[5];
    const float* b1    = (const float*)d_in[6];
    const float* ln_g  = (const float*)d_in[7];
    const float* ln_b  = (const float*)d_in[8];
    const float* w2    = (const float*)d_in[9];
    const float* b2    = (const float*)d_in[10];
    const float* tpl   = (const float*)d_in[11];
    const int*   kptr  = (const int*)d_in[12];
    float* out = (float*)d_out;

    void *p_qkv, *p_h;
    void *pA1, *pA2, *pA3, *pB1, *pB2, *pB3, *pW1, *pW2, *pW3;
    cudaGetSymbolAddress(&p_qkv, g_qkv);
    cudaGetSymbolAddress(&p_h,   g_h);
    cudaGetSymbolAddress(&pA1, g_A1); cudaGetSymbolAddress(&pA2, g_A2);
    cudaGetSymbolAddress(&pA3, g_A3);
    cudaGetSymbolAddress(&pB1, g_B1); cudaGetSymbolAddress(&pB2, g_B2);
    cudaGetSymbolAddress(&pB3, g_B3);
    cudaGetSymbolAddress(&pW1, g_W1); cudaGetSymbolAddress(&pW2, g_W2);
    cudaGetSymbolAddress(&pW3, g_W3);
    float* qkv = (float*)p_qkv;
    float* hb  = (float*)p_h;
    __nv_bfloat16 *A1=(__nv_bfloat16*)pA1, *A2=(__nv_bfloat16*)pA2, *A3=(__nv_bfloat16*)pA3;
    __nv_bfloat16 *B1=(__nv_bfloat16*)pB1, *B2=(__nv_bfloat16*)pB2, *B3=(__nv_bfloat16*)pB3;
    __nv_bfloat16 *W1=(__nv_bfloat16*)pW1, *W2=(__nv_bfloat16*)pW2, *W3=(__nv_bfloat16*)pW3;

    cudaFuncSetAttribute((const void*)gemm_bf<false,false>,
                         cudaFuncAttributeMaxDynamicSharedMemorySize, GSM_SIZE);
    cudaFuncSetAttribute((const void*)gemm_bf<true,true>,
                         cudaFuncAttributeMaxDynamicSharedMemorySize, GSM_SIZE);
    cudaFuncSetAttribute((const void*)attn_kernel,
                         cudaFuncAttributeMaxDynamicSharedMemorySize, ASM_FLOATS*4);

    const int gy = (RTOT + 127) / 128;   // 25

    split_all<<<(SPLIT_T4 + 255)/256, 256>>>(in_w, out_w, w1, F);
    gemm_bf<false,false><<<dim3(12, gy), 256, GSM_SIZE>>>(A1, A2, A3, W1, W2, W3,
                                                          in_b, nullptr, qkv, RTOT, DD, 1536);
    attn_kernel<<<dim3(7, HH, BB), 256, ASM_FLOATS*4>>>();
    gemm_bf<true,true><<<dim3(4, gy), 256, GSM_SIZE>>>(A1, A2, A3,
        W1+1536*DD, W2+1536*DD, W3+1536*DD, out_b, F, hb, RTOT, DD, 512);
    gemm_bf<false,false><<<dim3(4, gy), 256, GSM_SIZE>>>(B1, B2, B3,
        W1+2048*DD, W2+2048*DD, W3+2048*DD, b1, nullptr, hb, RTOT, DD, 512);
    ln_decomp<<<RTOT, 256>>>(hb, ln_g, ln_b, w2, b2, F, tpl, kptr, out);
}

// round 17
// speedup vs baseline: 1.0921x; 1.0921x over previous
#include <cuda_runtime.h>
#include <cuda_bf16.h>
#include <math.h>
#include <stdint.h>

#define BB 16
#define NN 196
#define DD 512
#define MM 20
#define HH 8
#define HD 64
#define RTOT (BB*NN)   /* 3136 */
#define WROWS 2560     /* in_w 1536 + out_w 512 + w1 512 */

// ---------------- scratch (device globals; no allocation) ----------------
__device__ float g_qkv[RTOT*3*DD];
__device__ float g_h[RTOT*DD];
__device__ __nv_bfloat16 g_A1[RTOT*DD], g_A2[RTOT*DD], g_A3[RTOT*DD];
__device__ __nv_bfloat16 g_B1[RTOT*DD], g_B2[RTOT*DD], g_B3[RTOT*DD];
__device__ __nv_bfloat16 g_W1[WROWS*DD], g_W2[WROWS*DD], g_W3[WROWS*DD];

// ---------------- warp helpers ----------------
__device__ __forceinline__ float warp_sum(float v){
#pragma unroll
    for (int off=16; off; off>>=1) v += __shfl_xor_sync(0xffffffffu, v, off);
    return v;
}
__device__ __forceinline__ float warp_max(float v){
#pragma unroll
    for (int off=16; off; off>>=1) v = fmaxf(v, __shfl_xor_sync(0xffffffffu, v, off));
    return v;
}

// ---------------- mma.sync / cp.async helpers ----------------
__device__ __forceinline__ uint32_t smem_u32(const void* p){
    uint32_t a;
    asm("{ .reg .u64 t; cvta.to.shared.u64 t, %1; cvt.u32.u64 %0, t; }" : "=r"(a) : "l"(p));
    return a;
}
__device__ __forceinline__ void ldm4(uint32_t* r, uint32_t addr){
    asm volatile("ldmatrix.sync.aligned.m8n8.x4.shared.b16 {%0,%1,%2,%3}, [%4];"
        : "=r"(r[0]),"=r"(r[1]),"=r"(r[2]),"=r"(r[3]) : "r"(addr));
}
__device__ __forceinline__ void mma16816(float* c, const uint32_t* a, const uint32_t* b){
    asm volatile("mma.sync.aligned.m16n8k16.row.col.f32.bf16.bf16.f32 "
        "{%0,%1,%2,%3}, {%4,%5,%6,%7}, {%8,%9}, {%0,%1,%2,%3};"
        : "+f"(c[0]),"+f"(c[1]),"+f"(c[2]),"+f"(c[3])
        : "r"(a[0]),"r"(a[1]),"r"(a[2]),"r"(a[3]), "r"(b[0]),"r"(b[1]));
}
__device__ __forceinline__ void cp16(uint32_t dst, const void* src){
    uint64_t g = __cvta_generic_to_global(src);
    asm volatile("cp.async.ca.shared.global [%0], [%1], 16;" :: "r"(dst), "l"(g) : "memory");
}

// 3-way bf16 cascade split: v = h1 + h2 + h3 + O(2^-27 |v|)
__device__ __forceinline__ void split3(float v, uint32_t& t1, uint32_t& t2, uint32_t& t3){
    __nv_bfloat16 h1 = __float2bfloat16_rn(v);
    float r1 = v - __bfloat162float(h1);
    __nv_bfloat16 h2 = __float2bfloat16_rn(r1);
    float r2 = r1 - __bfloat162float(h2);
    __nv_bfloat16 h3 = __float2bfloat16_rn(r2);
    t1 = (uint32_t)__bfloat16_as_ushort(h1);
    t2 = (uint32_t)__bfloat16_as_ushort(h2);
    t3 = (uint32_t)__bfloat16_as_ushort(h3);
}
__device__ __forceinline__ __nv_bfloat16 asbf(uint32_t t){
    return __ushort_as_bfloat16((unsigned short)t);
}

// ---------------- combined pre-split: weights + F in ONE launch -------------
#define SPLIT_W4 (WROWS*128)
#define SPLIT_T4 (SPLIT_W4 + RTOT*128)

__global__ void __launch_bounds__(256) split_all(
    const float* __restrict__ in_w, const float* __restrict__ out_w,
    const float* __restrict__ w1, const float* __restrict__ F)
{
    int i = blockIdx.x*256 + threadIdx.x;
    if (i >= SPLIT_T4) return;
    const float* src; size_t off;
    __nv_bfloat16 *d1, *d2, *d3; size_t dof;
    if (i < SPLIT_W4){
        int row = i >> 7;
        if (row < 1536){ src = in_w;  off = i; }
        else if (row < 2048){ src = out_w; off = i - (size_t)1536*128; }
        else { src = w1; off = i - (size_t)2048*128; }
        d1 = g_W1; d2 = g_W2; d3 = g_W3; dof = i;
    } else {
        src = F; off = i - SPLIT_W4;
        d1 = g_A1; d2 = g_A2; d3 = g_A3; dof = i - SPLIT_W4;
    }
    float4 v = ((const float4*)src)[off];
    uint32_t x1,x2,x3, y1,y2,y3, z1,z2,z3, u1,u2,u3;
    split3(v.x, x1,x2,x3); split3(v.y, y1,y2,y3);
    split3(v.z, z1,z2,z3); split3(v.w, u1,u2,u3);
    *(uint2*)&d1[dof*4] = make_uint2(x1|(y1<<16), z1|(u1<<16));
    *(uint2*)&d2[dof*4] = make_uint2(x2|(y2<<16), z2|(u2<<16));
    *(uint2*)&d3[dof*4] = make_uint2(x3|(y3<<16), z3|(u3<<16));
}

// ---------------- pure-bf16 GEMM: 64x128 tile, register-staged, 1 sync/chunk
// (R13 occupancy config + R6 mainloop structure: the measured-best combo)
#define TILE_A   4096                    /* 64 rows x 32 bf16 x 2B */
#define TILE_W   8192                    /* 128 rows x 32 bf16 x 2B */
#define STAGE_B  (3*TILE_A + 3*TILE_W)   /* 36864 */
#define GSM_SIZE (2*STAGE_B)             /* 73728; 2 CTAs/SM */

template<bool RES, bool SPLITOUT>
__global__ void __launch_bounds__(256) gemm_bf(
    const __nv_bfloat16* __restrict__ A1, const __nv_bfloat16* __restrict__ A2,
    const __nv_bfloat16* __restrict__ A3,
    const __nv_bfloat16* __restrict__ W1, const __nv_bfloat16* __restrict__ W2,
    const __nv_bfloat16* __restrict__ W3,
    const float* __restrict__ bias, const float* __restrict__ res,
    float* __restrict__ C, int R, int K, int O)
{
    extern __shared__ __align__(128) char smem[];
    const uint32_t sb = smem_u32(smem);
    const int tid = threadIdx.x, lane = tid & 31, wid = tid >> 5;
    const int rb = blockIdx.y * 64, ob = blockIdx.x * 128;
    const int wm = wid & 1, wn = wid >> 1;     // warp tile rows wm*32, cols wn*32

    float acc[2][4][4];
#pragma unroll
    for (int i=0;i<2;i++)
#pragma unroll
        for (int j=0;j<4;j++)
#pragma unroll
            for (int q=0;q<4;q++) acc[i][j][q]=0.f;

    const __nv_bfloat16* As[3] = {A1, A2, A3};
    const __nv_bfloat16* Ws[3] = {W1, W2, W3};

    // per-thread staging coordinates
    const int cr = tid >> 2, cq = tid & 3;     // row 0..63, 16B seg 0..3
    int gra = rb + cr; if (gra >= R) gra = R - 1;
    uint32_t aoff = (uint32_t)(cr*64 + cq*16);        aoff ^= (aoff>>3) & 0x30u;
    uint32_t woff0 = aoff;                              /* same pattern, rows 0..63 */
    uint32_t woff1 = (uint32_t)((cr+64)*64 + cq*16);  woff1 ^= (woff1>>3) & 0x30u;

    uint4 ua[3], uw0[3], uw1[3];
    auto load_chunk = [&](int k0){
#pragma unroll
        for (int t=0;t<3;t++){
            ua[t]  = *(const uint4*)(As[t] + (size_t)gra*K + k0 + cq*8);
            uw0[t] = *(const uint4*)(Ws[t] + (size_t)(ob + cr)*K + k0 + cq*8);
            uw1[t] = *(const uint4*)(Ws[t] + (size_t)(ob + cr + 64)*K + k0 + cq*8);
        }
    };
    auto store_chunk = [&](int s){
        char* base = smem + s*STAGE_B;
#pragma unroll
        for (int t=0;t<3;t++){
            *(uint4*)(base + t*TILE_A + aoff) = ua[t];
            *(uint4*)(base + 3*TILE_A + t*TILE_W + woff0) = uw0[t];
            *(uint4*)(base + 3*TILE_A + t*TILE_W + woff1) = uw1[t];
        }
    };

    load_chunk(0);
    store_chunk(0);
    __syncthreads();

    const int NTc = K / 32;
    const int npair[3] = {3, 2, 1};   // a1*{w1,w2,w3}, a2*{w1,w2}, a3*{w1}

    for (int c = 0; c < NTc; c++){
        if (c+1 < NTc) load_chunk((c+1)*32);   // LDG latency hidden by compute below

        const uint32_t stg = sb + (uint32_t)(c & 1)*STAGE_B;
#pragma unroll
        for (int ks = 0; ks < 2; ks++){
#pragma unroll
            for (int ai = 0; ai < 3; ai++){
                uint32_t afr[2][4];
#pragma unroll
                for (int mt = 0; mt < 2; mt++){
                    uint32_t row = (uint32_t)(wm*32 + mt*16 + (lane & 15));
                    uint32_t off = row*64 + (uint32_t)(ks*32) + (uint32_t)((lane >> 4) << 4);
                    off ^= (off >> 3) & 0x30u;
                    ldm4(afr[mt], stg + ai*TILE_A + off);
                }
#pragma unroll
                for (int wj = 0; wj < 3; wj++){
                    if (wj >= npair[ai]) break;
                    uint32_t bfr[4][2];
#pragma unroll
                    for (int nt2 = 0; nt2 < 2; nt2++){
                        uint32_t row = (uint32_t)(wn*32 + nt2*16 + ((lane >> 4) << 3) + (lane & 7));
                        uint32_t off = row*64 + (uint32_t)(ks*32) + (uint32_t)(((lane >> 3) & 1) << 4);
                        off ^= (off >> 3) & 0x30u;
                        uint32_t r4[4];
                        ldm4(r4, stg + 3*TILE_A + wj*TILE_W + off);
                        bfr[nt2*2][0]=r4[0];   bfr[nt2*2][1]=r4[1];
                        bfr[nt2*2+1][0]=r4[2]; bfr[nt2*2+1][1]=r4[3];
                    }
#pragma unroll
                    for (int mt = 0; mt < 2; mt++)
#pragma unroll
                        for (int nt = 0; nt < 4; nt++)
                            mma16816(acc[mt][nt], afr[mt], bfr[nt]);
                }
            }
        }

        if (c+1 < NTc) store_chunk((c+1) & 1);  // overwrites chunk c-1 buffer (safe)
        __syncthreads();
    }

    // ---- epilogue ----
    float* Cs = (float*)smem;
    {
        const int r0 = wm*32 + (lane >> 2);
        const int c0 = wn*32 + 2*(lane & 3);
#pragma unroll
        for (int mt = 0; mt < 2; mt++)
#pragma unroll
            for (int nt = 0; nt < 4; nt++){
                int row = r0 + mt*16, col = c0 + nt*8;
                Cs[row*129 + col]       = acc[mt][nt][0];
                Cs[row*129 + col + 1]   = acc[mt][nt][1];
                Cs[(row+8)*129 + col]   = acc[mt][nt][2];
                Cs[(row+8)*129 + col+1] = acc[mt][nt][3];
            }
    }
    __syncthreads();

    for (int idx = tid; idx < 64*128; idx += 256){
        int row = idx >> 7, c = idx & 127;
        int r = rb + row;
        if (r < R){
            float v = Cs[row*129 + c] + bias[ob + c];
            size_t g = (size_t)r*O + ob + c;
            if (RES) v += res[g];
            if (SPLITOUT){
                uint32_t t1,t2,t3;
                split3(v, t1,t2,t3);
                g_B1[g] = asbf(t1); g_B2[g] = asbf(t2); g_B3[g] = asbf(t3);
            } else {
                C[g] = v;
            }
        }
    }
}

// ---------------- attention: cp.async double-buffered K/V ------------------
#define ASM_Q   0
#define ASM_K0  1904
#define ASM_K1  5236
#define ASM_V0  8568
#define ASM_V1  11900
#define ASM_S   15232
#define ASM_FLOATS 16688   /* x4 = 66752 bytes */

__global__ void __launch_bounds__(256) attn_kernel()
{
    extern __shared__ __align__(16) float asmem[];
    const int qc = blockIdx.x, h = blockIdx.y, b = blockIdx.z;
    const int r0 = qc*28;
    const int tid = threadIdx.x, lane = tid & 31, w = tid >> 5;

    float* Qs = asmem + ASM_Q;
    float* S  = asmem + ASM_S;
    const uint32_t kbu[2] = {smem_u32(asmem + ASM_K0), smem_u32(asmem + ASM_K1)};
    const uint32_t vbu[2] = {smem_u32(asmem + ASM_V0), smem_u32(asmem + ASM_V1)};

    auto issue = [&](int t){
        const int buf = t & 1;
        for (int idx = tid; idx < 784; idx += 256){
            int j = idx >> 4, seg = idx & 15;
            size_t gb = (size_t)(b*NN + t*49 + j)*1536 + h*64 + seg*4;
            cp16(kbu[buf] + j*272 + seg*16, g_qkv + gb + 512);
            cp16(vbu[buf] + j*272 + seg*16, g_qkv + gb + 1024);
        }
        asm volatile("cp.async.commit_group;" ::: "memory");
    };

    issue(0);
    for (int idx=tid; idx<28*64; idx+=256){
        int row = idx>>6, kx = idx&63;
        Qs[row*68+kx] = g_qkv[(size_t)(b*NN + r0+row)*1536 + h*64 + kx];
    }

    const int nrows = (w<4)?4:3;
    float mrun[4], lrun[4], o0[4], o1[4];
#pragma unroll
    for (int rr=0; rr<4; rr++){ mrun[rr]=-1e30f; lrun[rr]=0.f; o0[rr]=0.f; o1[rr]=0.f; }

    const int srow = tid >> 3, jg = tid & 7;

    for (int t=0;t<4;t++){
        __syncthreads();
        if (t<3){
            issue(t+1);
            asm volatile("cp.async.wait_group 1;" ::: "memory");
        } else {
            asm volatile("cp.async.wait_group 0;" ::: "memory");
        }
        __syncthreads();

        const int buf = t & 1;
        const float* Ks = asmem + (buf ? ASM_K1 : ASM_K0);
        const float* Vs = asmem + (buf ? ASM_V1 : ASM_V0);

        if (srow < 28){
            float acc[7];
#pragma unroll
            for (int jj=0;jj<7;jj++) acc[jj]=0.f;
            const float4* q4 = (const float4*)&Qs[srow*68];
#pragma unroll
            for (int kx=0; kx<16; kx++){
                float4 qa = q4[kx];
#pragma unroll
                for (int jj=0;jj<7;jj++){
                    int j = jg + 8*jj;
                    if (j < 49){
                        float4 ka = *(const float4*)&Ks[j*68 + kx*4];
                        acc[jj] += qa.x*ka.x + qa.y*ka.y + qa.z*ka.z + qa.w*ka.w;
                    }
                }
            }
#pragma unroll
            for (int jj=0;jj<7;jj++){
                int j = jg + 8*jj;
                if (j < 49) S[srow*52+j] = acc[jj]*0.125f;
            }
        }
        __syncthreads();

#pragma unroll
        for (int rr=0; rr<4; rr++){
            if (rr >= nrows) break;
            int row = w + 8*rr;
            float s0 = (lane<49) ? S[row*52+lane]    : -1e30f;
            float s1 = (lane<17) ? S[row*52+lane+32] : -1e30f;
            float tm = warp_max(fmaxf(s0,s1));
            float mnew = fmaxf(mrun[rr], tm);
            float alpha = __expf(mrun[rr]-mnew);
            float p0 = (lane<49) ? __expf(s0-mnew) : 0.f;
            float p1 = (lane<17) ? __expf(s1-mnew) : 0.f;
            float psum = warp_sum(p0+p1);
            lrun[rr] = lrun[rr]*alpha + psum;
            mrun[rr] = mnew;
            if (lane<49) S[row*52+lane]    = p0;
            if (lane<17) S[row*52+lane+32] = p1;
            o0[rr]*=alpha; o1[rr]*=alpha;
        }
        __syncwarp();

#pragma unroll 3
        for (int j4=0; j4<12; j4++){
            const int jb2 = j4*4;
            float2 va0 = *(const float2*)&Vs[(jb2+0)*68 + 2*lane];
            float2 va1 = *(const float2*)&Vs[(jb2+1)*68 + 2*lane];
            float2 va2 = *(const float2*)&Vs[(jb2+2)*68 + 2*lane];
            float2 va3 = *(const float2*)&Vs[(jb2+3)*68 + 2*lane];
#pragma unroll
            for (int rr=0; rr<4; rr++){
                if (rr >= nrows) break;
                float4 p = *(const float4*)&S[(w + 8*rr)*52 + jb2];
                o0[rr] += p.x*va0.x + p.y*va1.x + p.z*va2.x + p.w*va3.x;
                o1[rr] += p.x*va0.y + p.y*va1.y + p.z*va2.y + p.w*va3.y;
            }
        }
        {
            float2 v48 = *(const float2*)&Vs[48*68 + 2*lane];
#pragma unroll
            for (int rr=0; rr<4; rr++){
                if (rr >= nrows) break;
                float pj = S[(w + 8*rr)*52 + 48];
                o0[rr] += pj * v48.x;
                o1[rr] += pj * v48.y;
            }
        }
    }
    for (int rr=0; rr<nrows; rr++){
        int row = w + 8*rr;
        float inv = 1.f/lrun[rr];
        size_t base = (size_t)(b*NN + r0+row)*512 + h*64 + 2*lane;
        uint32_t t1,t2,t3;
        split3(o0[rr]*inv, t1,t2,t3);
        g_A1[base] = asbf(t1); g_A2[base] = asbf(t2); g_A3[base] = asbf(t3);
        split3(o1[rr]*inv, t1,t2,t3);
        g_A1[base+1] = asbf(t1); g_A2[base+1] = asbf(t2); g_A3[base+1] = asbf(t3);
    }
}

// ---------------- fused LN + GELU + w2 + decompose --------------------------
__global__ void __launch_bounds__(256) ln_decomp(
    const float* __restrict__ hin, const float* __restrict__ lng,
    const float* __restrict__ lnb, const float* __restrict__ w2,
    const float* __restrict__ b2,
    const float* __restrict__ F, const float* __restrict__ tpl,
    const int* __restrict__ kptr, float* __restrict__ out)
{
    const int r = blockIdx.x, tid = threadIdx.x, lane = tid&31, w = tid>>5;
    __shared__ float fs[512];
    __shared__ float gs[512];
    __shared__ float red[16];
    __shared__ int hist[8][256];
    __shared__ unsigned int thr_s[MM];
    __shared__ float scale_s[MM];
    __shared__ unsigned int eqmask_s[MM][16];

    float x0 = hin[(size_t)r*512 + tid];
    float x1 = hin[(size_t)r*512 + tid + 256];
    fs[tid]     = F[(size_t)r*512 + tid];
    fs[tid+256] = F[(size_t)r*512 + tid + 256];

    float s  = warp_sum(x0 + x1);
    float sq = warp_sum(x0*x0 + x1*x1);
    if (lane==0){ red[w]=s; red[w+8]=sq; }
    __syncthreads();
    if (tid==0){
        float S=0,Q=0;
#pragma unroll
        for (int i=0;i<8;i++){ S+=red[i]; Q+=red[i+8]; }
        red[0]=S; red[1]=Q;
    }
    __syncthreads();
    float mean = red[0]*(1.f/512.f);
    float var  = red[1]*(1.f/512.f) - mean*mean;
    float rstd = rsqrtf(var + 1e-5f);
    {
        float y0 = (x0-mean)*rstd*lng[tid]     + lnb[tid];
        float y1 = (x1-mean)*rstd*lng[tid+256] + lnb[tid+256];
        gs[tid]     = 0.5f*y0*(1.f+erff(y0*0.70710678118654752f));
        gs[tid+256] = 0.5f*y1*(1.f+erff(y1*0.70710678118654752f));
    }
    __syncthreads();

    const int kval = *kptr;   // 51
    const int nm = (w<4) ? 3 : 2;
    float qpv[3];
    for (int i=0; i<nm; i++){
        int m = w + 8*i;
        float acc = 0.f;
#pragma unroll
        for (int j=0;j<16;j++){
            int d = lane + 32*j;
            acc += gs[d]*w2[m*512+d];
        }
        qpv[i] = warp_sum(acc) + b2[m];
    }

    for (int i=0; i<nm; i++){
        int m = w + 8*i;
        float p[16]; unsigned int u[16];
#pragma unroll
        for (int j=0;j<16;j++){
            int d = lane + 32*j;
            p[j] = fs[d]*tpl[m*512+d];
            u[j] = __float_as_uint(fabsf(p[j]));
        }
        unsigned int pref=0u, pmask=0u; int kk = kval;
        const int shifts[4]  = {23,15,7,0};
        const unsigned int dmasks[4] = {0xFFu,0xFFu,0xFFu,0x7Fu};
#pragma unroll
        for (int ps=0; ps<4; ps++){
            const int sh = shifts[ps]; const unsigned int dm = dmasks[ps];
            for (int bI=lane; bI<256; bI+=32) hist[w][bI]=0;
            __syncwarp();
#pragma unroll
            for (int j=0;j<16;j++){
                if ((u[j] & pmask) == pref)
                    atomicAdd(&hist[w][(u[j]>>sh)&dm], 1);
            }
            __syncwarp();
            int base = 255 - 8*lane;
            int s8 = 0;
#pragma unroll
            for (int j=0;j<8;j++) s8 += hist[w][base-j];
            int incl = s8;
#pragma unroll
            for (int off=1; off<32; off<<=1){
                int v = __shfl_up_sync(0xffffffffu, incl, off);
                if (lane>=off) incl += v;
            }
            int excl = incl - s8;
            int dig = -1, kk2 = 0;
            if (excl < kk && incl >= kk){
                int run = excl;
#pragma unroll
                for (int j=0;j<8;j++){
                    int hc = hist[w][base-j];
                    if (dig<0 && run+hc >= kk){ dig = base-j; kk2 = kk-run; }
                    run += hc;
                }
            }
            unsigned int bal = __ballot_sync(0xffffffffu, dig>=0);
            int src = __ffs(bal)-1;
            dig = __shfl_sync(0xffffffffu, dig, src);
            kk  = __shfl_sync(0xffffffffu, kk2, src);
            pref  |= ((unsigned int)dig) << sh;
            pmask |= dm << sh;
            __syncwarp();
        }
        const unsigned int thr = pref;
        const int needeq = kk;

        if (lane<16) eqmask_s[m][lane]=0u;
        __syncwarp();
        float ss = 0.f; int eqbase = 0;
#pragma unroll
        for (int j=0;j<16;j++){
            bool eq = (u[j]==thr);
            unsigned int eb = __ballot_sync(0xffffffffu, eq);
            bool esel = eq && (eqbase + __popc(eb & ((1u<<lane)-1u)) < needeq);
            eqbase += __popc(eb);
            unsigned int sb2 = __ballot_sync(0xffffffffu, esel);
            if (lane==0) eqmask_s[m][j] = sb2;
            if (u[j] > thr || esel) ss += p[j]*p[j];
        }
        ss = warp_sum(ss);
        if (lane==0){
            float q = qpv[i];
            float nrm = fabsf(q)*sqrtf(ss);
            scale_s[m] = q / fmaxf(nrm, 1e-6f);
            thr_s[m]   = thr;
        }
    }
    __syncthreads();

    const size_t obase = (size_t)r * (512*MM);
    for (int base = tid*4; base < 512*MM; base += 1024){
        float4 vv;
        float* pv4 = (float*)&vv;
#pragma unroll
        for (int e=0;e<4;e++){
            int lin = base + e;
            int d = lin / MM, m = lin - d*MM;
            float pv = fs[d]*tpl[m*512+d];
            unsigned int uu = __float_as_uint(fabsf(pv));
            unsigned int thr = thr_s[m];
            bool sel = (uu > thr) ||
                       (uu == thr && ((eqmask_s[m][d>>5] >> (d&31)) & 1u));
            pv4[e] = sel ? pv*scale_s[m] : 0.f;
        }
        *(float4*)&out[obase + base] = vv;
    }
}

// ---------------- launch ----------------
extern "C" void kernel_launch(void* const* d_in, const int* in_sizes, int n_in,
                              void* d_out, int out_size)
{
    (void)in_sizes; (void)n_in; (void)out_size;
    const float* F     = (const float*)d_in[0];
    const float* in_w  = (const float*)d_in[1];
    const float* in_b  = (const float*)d_in[2];
    const float* out_w = (const float*)d_in[3];
    const float* out_b = (const float*)d_in[4];
    const float* w1    = (const float*)d_in[5];
    const float* b1    = (const float*)d_in[6];
    const float* ln_g  = (const float*)d_in[7];
    const float* ln_b  = (const float*)d_in[8];
    const float* w2    = (const float*)d_in[9];
    const float* b2    = (const float*)d_in[10];
    const float* tpl   = (const float*)d_in[11];
    const int*   kptr  = (const int*)d_in[12];
    float* out = (float*)d_out;

    void *p_qkv, *p_h;
    void *pA1, *pA2, *pA3, *pB1, *pB2, *pB3, *pW1, *pW2, *pW3;
    cudaGetSymbolAddress(&p_qkv, g_qkv);
    cudaGetSymbolAddress(&p_h,   g_h);
    cudaGetSymbolAddress(&pA1, g_A1); cudaGetSymbolAddress(&pA2, g_A2);
    cudaGetSymbolAddress(&pA3, g_A3);
    cudaGetSymbolAddress(&pB1, g_B1); cudaGetSymbolAddress(&pB2, g_B2);
    cudaGetSymbolAddress(&pB3, g_B3);
    cudaGetSymbolAddress(&pW1, g_W1); cudaGetSymbolAddress(&pW2, g_W2);
    cudaGetSymbolAddress(&pW3, g_W3);
    float* qkv = (float*)p_qkv;
    float* hb  = (float*)p_h;
    __nv_bfloat16 *A1=(__nv_bfloat16*)pA1, *A2=(__nv_bfloat16*)pA2, *A3=(__nv_bfloat16*)pA3;
    __nv_bfloat16 *B1=(__nv_bfloat16*)pB1, *B2=(__nv_bfloat16*)pB2, *B3=(__nv_bfloat16*)pB3;
    __nv_bfloat16 *W1=(__nv_bfloat16*)pW1, *W2=(__nv_bfloat16*)pW2, *W3=(__nv_bfloat16*)pW3;

    cudaFuncSetAttribute((const void*)gemm_bf<false,false>,
                         cudaFuncAttributeMaxDynamicSharedMemorySize, GSM_SIZE);
    cudaFuncSetAttribute((const void*)gemm_bf<true,true>,
                         cudaFuncAttributeMaxDynamicSharedMemorySize, GSM_SIZE);
    cudaFuncSetAttribute((const void*)attn_kernel,
                         cudaFuncAttributeMaxDynamicSharedMemorySize, ASM_FLOATS*4);

    const int gy = (RTOT + 63) / 64;   // 49

    split_all<<<(SPLIT_T4 + 255)/256, 256>>>(in_w, out_w, w1, F);
    gemm_bf<false,false><<<dim3(12, gy), 256, GSM_SIZE>>>(A1, A2, A3, W1, W2, W3,
                                                          in_b, nullptr, qkv, RTOT, DD, 1536);
    attn_kernel<<<dim3(7, HH, BB), 256, ASM_FLOATS*4>>>();
    gemm_bf<true,true><<<dim3(4, gy), 256, GSM_SIZE>>>(A1, A2, A3,
        W1+1536*DD, W2+1536*DD, W3+1536*DD, out_b, F, hb, RTOT, DD, 512);
    gemm_bf<false,false><<<dim3(4, gy), 256, GSM_SIZE>>>(B1, B2, B3,
        W1+2048*DD, W2+2048*DD, W3+2048*DD, b1, nullptr, hb, RTOT, DD, 512);
    ln_decomp<<<RTOT, 256>>>(hb, ln_g, ln_b, w2, b2, F, tpl, kptr, out);
}